// round 10
// baseline (speedup 1.0000x reference)
#include <cuda_runtime.h>
#include <cuda_fp16.h>
#include <math.h>
#include <stdint.h>

#define NN 50000
#define EE 800000
#define CIN 256
#define COUT 256
#define NB 49            // scan blocks of 1024: 49*1024 = 50176 >= NN

// ---------------- scratch (static device globals; no allocation) -------------
__device__ __half g_xvh[(size_t)NN * 256]; // x @ Wv + bv  (fp16 storage)
__device__ float g_hlr[NN * 8];            // [sl(4) | sr(4)] raw
__device__ float g_agg[NN * 8];            // (hlr + conv)/(1+deg)
__device__ int   g_esrc[EE];               // src indices sorted by dst (CSR)
__device__ int   g_off[NN + 1];            // CSR offsets
__device__ int   g_cur[NN];                // scatter cursors
__device__ int   g_deg[NN];                // in-degree per dst
__device__ float g_watt[8 * 256];          // rows 0..3: Wl@att_l per head; 4..7: Wr@att_r
__device__ float g_batt[8];                // bias dotted with att vectors
__device__ float g_WvT[256 * 256];         // Wv transposed: g_WvT[n][k] = Wv[k][n]
__device__ int   g_bsum[64];               // per-block degree sums
__device__ int   g_boff[64];               // exclusive scan of block sums

// ---------------- fused setup: prep (blocks 0..7), trans (8..71), zero (72..267)
__global__ void k_setup(const float* __restrict__ Wl, const float* __restrict__ bl,
                        const float* __restrict__ Wr, const float* __restrict__ br,
                        const float* __restrict__ attl, const float* __restrict__ attr,
                        const float* __restrict__ Wv) {
    int b = blockIdx.x;
    if (b < 8) {
        int o = b, h = o & 3;
        const float* W   = (o < 4) ? Wl : Wr;
        const float* att = (o < 4) ? attl : attr;
        const float* bb  = (o < 4) ? bl : br;
        int c = threadIdx.x;
        float s = 0.f;
#pragma unroll 8
        for (int d = 0; d < 64; d++) s += W[c * 256 + h * 64 + d] * att[h * 64 + d];
        g_watt[o * 256 + c] = s;
        if (c == 0) {
            float sb = 0.f;
            for (int d = 0; d < 64; d++) sb += bb[h * 64 + d] * att[h * 64 + d];
            g_batt[o] = sb;
        }
    } else if (b < 72) {
        __shared__ float tile[32][33];
        int bb2 = b - 8;
        int bx = bb2 & 7, by = bb2 >> 3;
        int tx = threadIdx.x & 31, ty = threadIdx.x >> 5;
#pragma unroll
        for (int i = 0; i < 32; i += 8)
            tile[ty + i][tx] = Wv[(by * 32 + ty + i) * 256 + bx * 32 + tx];
        __syncthreads();
#pragma unroll
        for (int i = 0; i < 32; i += 8)
            g_WvT[(bx * 32 + ty + i) * 256 + by * 32 + tx] = tile[tx][ty + i];
    } else {
        int i = (b - 72) * 256 + threadIdx.x;
        if (i < NN) g_deg[i] = 0;
    }
}

// ---------------- per-node raw scores: warp per 16 nodes, watt in registers --
__global__ void __launch_bounds__(256) k_hlr(const float* __restrict__ x) {
    int wid = threadIdx.x >> 5, lane = threadIdx.x & 31;
    int gw = blockIdx.x * 8 + wid;              // 0..3127
    float4 w0[8], w1[8];
#pragma unroll
    for (int o = 0; o < 8; o++) {
        w0[o] = *(const float4*)&g_watt[o * 256 + lane * 8];
        w1[o] = *(const float4*)&g_watt[o * 256 + lane * 8 + 4];
    }
    int n0 = gw * 16;
    if (n0 >= NN) return;
    int n1 = n0 + 16; if (n1 > NN) n1 = NN;

    float4 x0 = *(const float4*)(x + (size_t)n0 * 256 + lane * 8);
    float4 x1 = *(const float4*)(x + (size_t)n0 * 256 + lane * 8 + 4);
    for (int n = n0; n < n1; n++) {
        float4 nx0, nx1;
        if (n + 1 < n1) {
            nx0 = *(const float4*)(x + (size_t)(n + 1) * 256 + lane * 8);
            nx1 = *(const float4*)(x + (size_t)(n + 1) * 256 + lane * 8 + 4);
        }
        float a[8];
#pragma unroll
        for (int o = 0; o < 8; o++) {
            a[o] = x0.x * w0[o].x + x0.y * w0[o].y + x0.z * w0[o].z + x0.w * w0[o].w
                 + x1.x * w1[o].x + x1.y * w1[o].y + x1.z * w1[o].z + x1.w * w1[o].w;
#pragma unroll
            for (int s = 16; s; s >>= 1) a[o] += __shfl_xor_sync(0xffffffffu, a[o], s);
        }
        if (lane == 0) {
#pragma unroll
            for (int o = 0; o < 8; o++) g_hlr[n * 8 + o] = a[o] + g_batt[o];
        }
        x0 = nx0; x1 = nx1;
    }
}

__global__ void k_count(const int* __restrict__ dst) {
    int e = blockIdx.x * blockDim.x + threadIdx.x;
    if (e < EE) atomicAdd(&g_deg[dst[e]], 1);
}

// ---- parallel 3-phase exclusive scan of g_deg -> g_off, g_cur ----
__global__ void k_bsum() {                 // grid NB, block 1024
    __shared__ int ssum[32];
    int b = blockIdx.x, t = threadIdx.x;
    int i = b * 1024 + t;
    int v = (i < NN) ? g_deg[i] : 0;
#pragma unroll
    for (int o = 16; o; o >>= 1) v += __shfl_xor_sync(0xffffffffu, v, o);
    if ((t & 31) == 0) ssum[t >> 5] = v;
    __syncthreads();
    if (t < 32) {
        int s = ssum[t];
#pragma unroll
        for (int o = 16; o; o >>= 1) s += __shfl_xor_sync(0xffffffffu, s, o);
        if (t == 0) g_bsum[b] = s;
    }
}

__global__ void k_bscan() {                // 1 block, 64 threads
    __shared__ int sh[64];
    int t = threadIdx.x;
    int v = (t < NB) ? g_bsum[t] : 0;
    sh[t] = v;
    __syncthreads();
    for (int o = 1; o < 64; o <<= 1) {
        int y = (t >= o) ? sh[t - o] : 0;
        __syncthreads();
        sh[t] += y;
        __syncthreads();
    }
    if (t < NB) g_boff[t] = sh[t] - v;     // exclusive
    if (t == NB - 1) g_off[NN] = sh[NB - 1];
}

__global__ void k_scan2() {                // grid NB, block 1024
    __shared__ int wsum[32];
    int b = blockIdx.x, t = threadIdx.x, lane = t & 31, wid = t >> 5;
    int i = b * 1024 + t;
    int v = (i < NN) ? g_deg[i] : 0;
    int xsc = v;
#pragma unroll
    for (int o = 1; o < 32; o <<= 1) { int y = __shfl_up_sync(0xffffffffu, xsc, o); if (lane >= o) xsc += y; }
    if (lane == 31) wsum[wid] = xsc;
    __syncthreads();
    if (wid == 0) {
        int s = wsum[lane];
#pragma unroll
        for (int o = 1; o < 32; o <<= 1) { int y = __shfl_up_sync(0xffffffffu, s, o); if (lane >= o) s += y; }
        wsum[lane] = s;
    }
    __syncthreads();
    int prefix = g_boff[b] + (wid ? wsum[wid - 1] : 0) + xsc - v;   // exclusive
    if (i < NN) { g_off[i] = prefix; g_cur[i] = prefix; }
}

__global__ void k_scatter(const int* __restrict__ src, const int* __restrict__ dst) {
    int e = blockIdx.x * blockDim.x + threadIdx.x;
    if (e < EE) {
        int d = dst[e];
        int pos = atomicAdd(&g_cur[d], 1);
        g_esrc[pos] = src[e];
    }
}

// agg[n][:] = (hlr[n][:] + sum_in hlr[src][:]) / (1 + deg)  — thread per node
__global__ void k_agg() {
    int n = blockIdx.x * blockDim.x + threadIdx.x;
    if (n >= NN) return;
    int s = g_off[n], e = g_off[n + 1];
    float4 c0 = *(const float4*)&g_hlr[n * 8];
    float4 c1 = *(const float4*)&g_hlr[n * 8 + 4];
    for (int j = s; j < e; j++) {
        int sr = g_esrc[j];
        float4 h0 = *(const float4*)&g_hlr[sr * 8];
        float4 h1 = *(const float4*)&g_hlr[sr * 8 + 4];
        c0.x += h0.x; c0.y += h0.y; c0.z += h0.z; c0.w += h0.w;
        c1.x += h1.x; c1.y += h1.y; c1.z += h1.z; c1.w += h1.w;
    }
    float inv = 1.0f / (1.0f + (float)(e - s));
    c0.x *= inv; c0.y *= inv; c0.z *= inv; c0.w *= inv;
    c1.x *= inv; c1.y *= inv; c1.z *= inv; c1.w *= inv;
    *(float4*)&g_agg[n * 8] = c0;
    *(float4*)&g_agg[n * 8 + 4] = c1;
}

// ---------------- tf32 mma.sync GEMM: g_xvh = half(x @ Wv + bv) --------------
__device__ __forceinline__ uint32_t f2tf(float f) {
    uint32_t u;
    asm("cvt.rna.tf32.f32 %0, %1;" : "=r"(u) : "f"(f));
    return u;
}

__global__ void __launch_bounds__(256) k_gemm_mma(const float* __restrict__ A,
                                                  const float* __restrict__ bias) {
    __shared__ uint32_t As[4096];   // [kstep(4)][mtile(8)][reg(4)][lane(32)]
    __shared__ uint32_t Bs[4096];   // [kstep(4)][ntile(16)][reg(2)][lane(32)]
    int t = threadIdx.x, lane = t & 31, wid = t >> 5;
    int row0 = (int)(blockIdx.x >> 1) * 128;
    int col0 = (int)(blockIdx.x & 1) * 128;
    int warp_m = wid & 1, warp_n = wid >> 1;

    float acc[4][4][4];
#pragma unroll
    for (int mt = 0; mt < 4; mt++)
#pragma unroll
        for (int nt = 0; nt < 4; nt++)
#pragma unroll
            for (int j = 0; j < 4; j++) acc[mt][nt][j] = 0.f;

    int sAaddr[4], sBaddr[4], aRow[4], bRow[4], abCol[4];
#pragma unroll
    for (int l = 0; l < 4; l++) {
        int i = t + l * 256;
        int r = i >> 3, cq = i & 7;
        aRow[l] = r; bRow[l] = r; abCol[l] = cq * 4;
        int ks = cq >> 1, u = cq & 1;
        int mtile = r >> 4, h = (r >> 3) & 1, g = r & 7;
        sAaddr[l] = ((ks * 8 + mtile) * 4 + (h + 2 * u)) * 32 + g * 4;
        int ntile = r >> 3;
        sBaddr[l] = ((ks * 16 + ntile) * 2 + u) * 32 + (r & 7) * 4;
    }

    uint4 ap[4], bp[4];
#pragma unroll
    for (int l = 0; l < 4; l++) {
        int grow = row0 + aRow[l];
        float4 v = make_float4(0.f, 0.f, 0.f, 0.f);
        if (grow < NN) v = *(const float4*)(A + (size_t)grow * 256 + abCol[l]);
        ap[l] = make_uint4(f2tf(v.x), f2tf(v.y), f2tf(v.z), f2tf(v.w));
        float4 w = *(const float4*)(g_WvT + (size_t)(col0 + bRow[l]) * 256 + abCol[l]);
        bp[l] = make_uint4(f2tf(w.x), f2tf(w.y), f2tf(w.z), f2tf(w.w));
    }

    for (int c = 0; c < 8; c++) {
#pragma unroll
        for (int l = 0; l < 4; l++) {
            *(uint4*)&As[sAaddr[l]] = ap[l];
            *(uint4*)&Bs[sBaddr[l]] = bp[l];
        }
        __syncthreads();
        if (c < 7) {
            int k0 = (c + 1) * 32;
#pragma unroll
            for (int l = 0; l < 4; l++) {
                int grow = row0 + aRow[l];
                float4 v = make_float4(0.f, 0.f, 0.f, 0.f);
                if (grow < NN) v = *(const float4*)(A + (size_t)grow * 256 + k0 + abCol[l]);
                ap[l] = make_uint4(f2tf(v.x), f2tf(v.y), f2tf(v.z), f2tf(v.w));
                float4 w = *(const float4*)(g_WvT + (size_t)(col0 + bRow[l]) * 256 + k0 + abCol[l]);
                bp[l] = make_uint4(f2tf(w.x), f2tf(w.y), f2tf(w.z), f2tf(w.w));
            }
        }
#pragma unroll
        for (int ks = 0; ks < 4; ks++) {
            uint32_t a[4][4], b[4][2];
#pragma unroll
            for (int mt = 0; mt < 4; mt++)
#pragma unroll
                for (int rg = 0; rg < 4; rg++)
                    a[mt][rg] = As[((ks * 8 + warp_m * 4 + mt) * 4 + rg) * 32 + lane];
#pragma unroll
            for (int nt = 0; nt < 4; nt++)
#pragma unroll
                for (int rg = 0; rg < 2; rg++)
                    b[nt][rg] = Bs[((ks * 16 + warp_n * 4 + nt) * 2 + rg) * 32 + lane];
#pragma unroll
            for (int mt = 0; mt < 4; mt++)
#pragma unroll
                for (int nt = 0; nt < 4; nt++) {
                    asm volatile(
                        "mma.sync.aligned.m16n8k8.row.col.f32.tf32.tf32.f32 "
                        "{%0,%1,%2,%3}, {%4,%5,%6,%7}, {%8,%9}, {%0,%1,%2,%3};"
                        : "+f"(acc[mt][nt][0]), "+f"(acc[mt][nt][1]),
                          "+f"(acc[mt][nt][2]), "+f"(acc[mt][nt][3])
                        : "r"(a[mt][0]), "r"(a[mt][1]), "r"(a[mt][2]), "r"(a[mt][3]),
                          "r"(b[nt][0]), "r"(b[nt][1]));
                }
        }
        __syncthreads();
    }

    int g = lane >> 2, tig = lane & 3;
#pragma unroll
    for (int mt = 0; mt < 4; mt++) {
        int rbase = row0 + warp_m * 64 + mt * 16;
#pragma unroll
        for (int h = 0; h < 2; h++) {
            int grow = rbase + h * 8 + g;
            if (grow < NN) {
                __half* orow = g_xvh + (size_t)grow * 256;
#pragma unroll
                for (int nt = 0; nt < 4; nt++) {
                    int col = col0 + warp_n * 32 + nt * 8 + tig * 2;
                    float2 o;
                    o.x = acc[mt][nt][h * 2 + 0] + bias[col];
                    o.y = acc[mt][nt][h * 2 + 1] + bias[col + 1];
                    *(__half2*)(orow + col) = __floats2half2_rn(o.x, o.y);
                }
            }
        }
    }
}

// ---------------- attention + output (warp per dst node) --------------------
__global__ void k_out(float* __restrict__ out) {
    int gw = (blockIdx.x * blockDim.x + threadIdx.x) >> 5;
    int lane = threadIdx.x & 31;
    if (gw >= NN) return;
    int s0 = g_off[gw], s1 = g_off[gw + 1];
    float4* orow = (float4*)(out + (size_t)gw * 256);
    if (s0 == s1) {
        float4 z = make_float4(0.f, 0.f, 0.f, 0.f);
        orow[lane] = z; orow[lane + 32] = z;
        return;
    }
    float srh[4];
#pragma unroll
    for (int h = 0; h < 4; h++) srh[h] = g_agg[gw * 8 + 4 + h];

    float m[4] = {-3.402823466e38f, -3.402823466e38f, -3.402823466e38f, -3.402823466e38f};
    for (int j = s0 + lane; j < s1; j += 32) {
        int s = g_esrc[j];
#pragma unroll
        for (int h = 0; h < 4; h++) {
            float e = g_agg[s * 8 + h] + srh[h];
            e = e > 0.f ? e : 0.2f * e;
            m[h] = fmaxf(m[h], e);
        }
    }
#pragma unroll
    for (int h = 0; h < 4; h++)
#pragma unroll
        for (int o = 16; o; o >>= 1) m[h] = fmaxf(m[h], __shfl_xor_sync(0xffffffffu, m[h], o));

    float den0 = 0.f, den1 = 0.f, den2 = 0.f, den3 = 0.f;
    float4 acc0 = make_float4(0.f, 0.f, 0.f, 0.f);
    float4 acc1 = acc0;
    bool hi = (lane & 16) != 0;
    for (int j = s0; j < s1; j++) {
        int s = g_esrc[j];
        float e0 = g_agg[s * 8 + 0] + srh[0]; e0 = e0 > 0.f ? e0 : 0.2f * e0;
        float e1 = g_agg[s * 8 + 1] + srh[1]; e1 = e1 > 0.f ? e1 : 0.2f * e1;
        float e2 = g_agg[s * 8 + 2] + srh[2]; e2 = e2 > 0.f ? e2 : 0.2f * e2;
        float e3 = g_agg[s * 8 + 3] + srh[3]; e3 = e3 > 0.f ? e3 : 0.2f * e3;
        float x0 = __expf(e0 - m[0]);
        float x1 = __expf(e1 - m[1]);
        float x2 = __expf(e2 - m[2]);
        float x3 = __expf(e3 - m[3]);
        den0 += x0; den1 += x1; den2 += x2; den3 += x3;
        const uint2* vr = (const uint2*)(g_xvh + (size_t)s * 256);
        uint2 p0 = vr[lane], p1 = vr[lane + 32];
        float2 a0 = __half22float2(*(__half2*)&p0.x);
        float2 a1 = __half22float2(*(__half2*)&p0.y);
        float2 b0 = __half22float2(*(__half2*)&p1.x);
        float2 b1 = __half22float2(*(__half2*)&p1.y);
        float w0 = hi ? x1 : x0;
        float w1 = hi ? x3 : x2;
        acc0.x += w0 * a0.x; acc0.y += w0 * a0.y; acc0.z += w0 * a1.x; acc0.w += w0 * a1.y;
        acc1.x += w1 * b0.x; acc1.y += w1 * b0.y; acc1.z += w1 * b1.x; acc1.w += w1 * b1.y;
    }
    float d0 = hi ? den1 : den0;
    float d1 = hi ? den3 : den2;
    float i0 = 1.f / fmaxf(d0, 1e-16f);
    float i1 = 1.f / fmaxf(d1, 1e-16f);
    acc0.x *= i0; acc0.y *= i0; acc0.z *= i0; acc0.w *= i0;
    acc1.x *= i1; acc1.y *= i1; acc1.z *= i1; acc1.w *= i1;
    orow[lane] = acc0;
    orow[lane + 32] = acc1;
}

// ---------------- launch ----------------
extern "C" void kernel_launch(void* const* d_in, const int* in_sizes, int n_in,
                              void* d_out, int out_size) {
    const float* x    = (const float*)d_in[0];
    const int*   src  = (const int*)d_in[1];
    const int*   dst  = (const int*)d_in[2];
    const float* Wl   = (const float*)d_in[3];
    const float* bl   = (const float*)d_in[4];
    const float* Wr   = (const float*)d_in[5];
    const float* br   = (const float*)d_in[6];
    const float* Wv   = (const float*)d_in[7];
    const float* bv   = (const float*)d_in[8];
    const float* attl = (const float*)d_in[9];
    const float* attr = (const float*)d_in[10];
    float* out = (float*)d_out;

    k_setup<<<72 + (NN + 255) / 256, 256>>>(Wl, bl, Wr, br, attl, attr, Wv);
    k_hlr<<<(NN + 127) / 128, 256>>>(x);          // 8 warps/block, 16 nodes/warp
    k_count<<<(EE + 255) / 256, 256>>>(dst);
    k_bsum<<<NB, 1024>>>();
    k_bscan<<<1, 64>>>();
    k_scan2<<<NB, 1024>>>();
    k_scatter<<<(EE + 255) / 256, 256>>>(src, dst);
    k_gemm_mma<<<((NN + 127) / 128) * 2, 256>>>(x, bv);
    k_agg<<<(NN + 255) / 256, 256>>>();
    k_out<<<(NN * 32 + 255) / 256, 256>>>(out);
}

// round 11
// speedup vs baseline: 1.5375x; 1.5375x over previous
#include <cuda_runtime.h>
#include <cuda_fp16.h>
#include <math.h>
#include <stdint.h>

#define NN 50000
#define EE 800000
#define CIN 256
#define COUT 256
#define NB 49            // scan blocks of 1024: 49*1024 = 50176 >= NN

// ---------------- scratch (static device globals; no allocation) -------------
__device__ __half g_xvh[(size_t)NN * 256]; // x @ Wv + bv  (fp16 storage)
__device__ float g_hlr[NN * 8];            // [sl(4) | sr(4)] raw
__device__ float g_agg[NN * 8];            // (hlr + conv)/(1+deg)
__device__ int   g_esrc[EE];               // src indices sorted by dst (CSR)
__device__ int   g_off[NN + 1];            // CSR offsets
__device__ int   g_cur[NN];                // scatter cursors
__device__ int   g_deg[NN];                // in-degree per dst
__device__ float g_watt[8 * 256];          // rows 0..3: Wl@att_l per head; 4..7: Wr@att_r
__device__ float g_batt[8];                // bias dotted with att vectors
__device__ float g_WvT[256 * 256];         // Wv transposed: g_WvT[n][k] = Wv[k][n]
__device__ int   g_bsum[64];               // per-block degree sums
__device__ int   g_boff[64];               // exclusive scan of block sums

// ---------------- fused setup: prep (blocks 0..7), trans (8..71), zero (72..)
__global__ void k_setup(const float* __restrict__ Wl, const float* __restrict__ bl,
                        const float* __restrict__ Wr, const float* __restrict__ br,
                        const float* __restrict__ attl, const float* __restrict__ attr,
                        const float* __restrict__ Wv) {
    int b = blockIdx.x;
    if (b < 8) {
        int o = b, h = o & 3;
        const float* W   = (o < 4) ? Wl : Wr;
        const float* att = (o < 4) ? attl : attr;
        const float* bb  = (o < 4) ? bl : br;
        int c = threadIdx.x;
        float s = 0.f;
#pragma unroll 8
        for (int d = 0; d < 64; d++) s += W[c * 256 + h * 64 + d] * att[h * 64 + d];
        g_watt[o * 256 + c] = s;
        if (c == 0) {
            float sb = 0.f;
            for (int d = 0; d < 64; d++) sb += bb[h * 64 + d] * att[h * 64 + d];
            g_batt[o] = sb;
        }
    } else if (b < 72) {
        __shared__ float tile[32][33];
        int bb2 = b - 8;
        int bx = bb2 & 7, by = bb2 >> 3;
        int tx = threadIdx.x & 31, ty = threadIdx.x >> 5;
#pragma unroll
        for (int i = 0; i < 32; i += 8)
            tile[ty + i][tx] = Wv[(by * 32 + ty + i) * 256 + bx * 32 + tx];
        __syncthreads();
#pragma unroll
        for (int i = 0; i < 32; i += 8)
            g_WvT[(bx * 32 + ty + i) * 256 + by * 32 + tx] = tile[tx][ty + i];
    } else {
        int i = (b - 72) * 256 + threadIdx.x;
        if (i < NN) g_deg[i] = 0;
    }
}

// per-node raw scores: thread per node, smem-staged x chunks, watt broadcast
// (exact R7-measured variant: 27.0us)
__global__ void __launch_bounds__(256) k_hlr(const float* __restrict__ x) {
    __shared__ float ws[8 * 256];     // watt, broadcast reads
    __shared__ float xs[256 * 36];    // 256 nodes x 32-k chunk, pitch 36
    int t = threadIdx.x;
    int n0 = blockIdx.x * 256;
    for (int i = t; i < 2048; i += 256) ws[i] = g_watt[i];
    float acc[8];
#pragma unroll
    for (int o = 0; o < 8; o++) acc[o] = 0.f;

    for (int c = 0; c < 8; c++) {
        int k0 = c * 32;
        __syncthreads();
#pragma unroll
        for (int p = 0; p < 8; p++) {
            int i = t + p * 256;
            int n = i >> 3, kq = i & 7;
            float4 v = make_float4(0.f, 0.f, 0.f, 0.f);
            int gn = n0 + n;
            if (gn < NN) v = *(const float4*)(x + (size_t)gn * 256 + k0 + kq * 4);
            *(float4*)&xs[n * 36 + kq * 4] = v;
        }
        __syncthreads();
        float4 xr[8];
#pragma unroll
        for (int q = 0; q < 8; q++) xr[q] = *(float4*)&xs[t * 36 + q * 4];
#pragma unroll
        for (int o = 0; o < 8; o++) {
            float s = 0.f;
#pragma unroll
            for (int q = 0; q < 8; q++) {
                float4 w = *(const float4*)&ws[o * 256 + k0 + q * 4];
                s += xr[q].x * w.x + xr[q].y * w.y + xr[q].z * w.z + xr[q].w * w.w;
            }
            acc[o] += s;
        }
    }
    int gn = n0 + t;
    if (gn < NN) {
#pragma unroll
        for (int o = 0; o < 8; o++) g_hlr[gn * 8 + o] = acc[o] + g_batt[o];
    }
}

__global__ void k_count(const int* __restrict__ dst) {
    int e = blockIdx.x * blockDim.x + threadIdx.x;
    if (e < EE) atomicAdd(&g_deg[dst[e]], 1);
}

// ---- parallel 3-phase exclusive scan of g_deg -> g_off, g_cur ----
__global__ void k_bsum() {                 // grid NB, block 1024
    __shared__ int ssum[32];
    int b = blockIdx.x, t = threadIdx.x;
    int i = b * 1024 + t;
    int v = (i < NN) ? g_deg[i] : 0;
#pragma unroll
    for (int o = 16; o; o >>= 1) v += __shfl_xor_sync(0xffffffffu, v, o);
    if ((t & 31) == 0) ssum[t >> 5] = v;
    __syncthreads();
    if (t < 32) {
        int s = ssum[t];
#pragma unroll
        for (int o = 16; o; o >>= 1) s += __shfl_xor_sync(0xffffffffu, s, o);
        if (t == 0) g_bsum[b] = s;
    }
}

__global__ void k_bscan() {                // 1 block, 64 threads
    __shared__ int sh[64];
    int t = threadIdx.x;
    int v = (t < NB) ? g_bsum[t] : 0;
    sh[t] = v;
    __syncthreads();
    for (int o = 1; o < 64; o <<= 1) {
        int y = (t >= o) ? sh[t - o] : 0;
        __syncthreads();
        sh[t] += y;
        __syncthreads();
    }
    if (t < NB) g_boff[t] = sh[t] - v;     // exclusive
    if (t == NB - 1) g_off[NN] = sh[NB - 1];
}

__global__ void k_scan2() {                // grid NB, block 1024
    __shared__ int wsum[32];
    int b = blockIdx.x, t = threadIdx.x, lane = t & 31, wid = t >> 5;
    int i = b * 1024 + t;
    int v = (i < NN) ? g_deg[i] : 0;
    int xsc = v;
#pragma unroll
    for (int o = 1; o < 32; o <<= 1) { int y = __shfl_up_sync(0xffffffffu, xsc, o); if (lane >= o) xsc += y; }
    if (lane == 31) wsum[wid] = xsc;
    __syncthreads();
    if (wid == 0) {
        int s = wsum[lane];
#pragma unroll
        for (int o = 1; o < 32; o <<= 1) { int y = __shfl_up_sync(0xffffffffu, s, o); if (lane >= o) s += y; }
        wsum[lane] = s;
    }
    __syncthreads();
    int prefix = g_boff[b] + (wid ? wsum[wid - 1] : 0) + xsc - v;   // exclusive
    if (i < NN) { g_off[i] = prefix; g_cur[i] = prefix; }
}

__global__ void k_scatter(const int* __restrict__ src, const int* __restrict__ dst) {
    int e = blockIdx.x * blockDim.x + threadIdx.x;
    if (e < EE) {
        int d = dst[e];
        int pos = atomicAdd(&g_cur[d], 1);
        g_esrc[pos] = src[e];
    }
}

// agg[n][f] = (hlr[n][f] + sum_in hlr[src][f]) / (1 + deg)  — 8 threads/node
__global__ void k_agg() {
    int idx = blockIdx.x * blockDim.x + threadIdx.x;
    if (idx >= NN * 8) return;
    int n = idx >> 3, f = idx & 7;
    int s = g_off[n], e = g_off[n + 1];
    float c = 0.f;
    for (int j = s; j < e; j++) c += g_hlr[g_esrc[j] * 8 + f];
    g_agg[idx] = (g_hlr[idx] + c) / (1.0f + (float)(e - s));
}

// ---------------- tf32 mma.sync GEMM: g_xvh = half(x @ Wv + bv) --------------
__device__ __forceinline__ uint32_t f2tf(float f) {
    uint32_t u;
    asm("cvt.rna.tf32.f32 %0, %1;" : "=r"(u) : "f"(f));
    return u;
}

__global__ void __launch_bounds__(256) k_gemm_mma(const float* __restrict__ A,
                                                  const float* __restrict__ bias) {
    __shared__ uint32_t As[4096];   // [kstep(4)][mtile(8)][reg(4)][lane(32)]
    __shared__ uint32_t Bs[4096];   // [kstep(4)][ntile(16)][reg(2)][lane(32)]
    int t = threadIdx.x, lane = t & 31, wid = t >> 5;
    int row0 = (int)(blockIdx.x >> 1) * 128;
    int col0 = (int)(blockIdx.x & 1) * 128;
    int warp_m = wid & 1, warp_n = wid >> 1;

    float acc[4][4][4];
#pragma unroll
    for (int mt = 0; mt < 4; mt++)
#pragma unroll
        for (int nt = 0; nt < 4; nt++)
#pragma unroll
            for (int j = 0; j < 4; j++) acc[mt][nt][j] = 0.f;

    int sAaddr[4], sBaddr[4], aRow[4], bRow[4], abCol[4];
#pragma unroll
    for (int l = 0; l < 4; l++) {
        int i = t + l * 256;
        int r = i >> 3, cq = i & 7;
        aRow[l] = r; bRow[l] = r; abCol[l] = cq * 4;
        int ks = cq >> 1, u = cq & 1;
        int mtile = r >> 4, h = (r >> 3) & 1, g = r & 7;
        sAaddr[l] = ((ks * 8 + mtile) * 4 + (h + 2 * u)) * 32 + g * 4;
        int ntile = r >> 3;
        sBaddr[l] = ((ks * 16 + ntile) * 2 + u) * 32 + (r & 7) * 4;
    }

    uint4 ap[4], bp[4];
#pragma unroll
    for (int l = 0; l < 4; l++) {
        int grow = row0 + aRow[l];
        float4 v = make_float4(0.f, 0.f, 0.f, 0.f);
        if (grow < NN) v = *(const float4*)(A + (size_t)grow * 256 + abCol[l]);
        ap[l] = make_uint4(f2tf(v.x), f2tf(v.y), f2tf(v.z), f2tf(v.w));
        float4 w = *(const float4*)(g_WvT + (size_t)(col0 + bRow[l]) * 256 + abCol[l]);
        bp[l] = make_uint4(f2tf(w.x), f2tf(w.y), f2tf(w.z), f2tf(w.w));
    }

    for (int c = 0; c < 8; c++) {
#pragma unroll
        for (int l = 0; l < 4; l++) {
            *(uint4*)&As[sAaddr[l]] = ap[l];
            *(uint4*)&Bs[sBaddr[l]] = bp[l];
        }
        __syncthreads();
        if (c < 7) {
            int k0 = (c + 1) * 32;
#pragma unroll
            for (int l = 0; l < 4; l++) {
                int grow = row0 + aRow[l];
                float4 v = make_float4(0.f, 0.f, 0.f, 0.f);
                if (grow < NN) v = *(const float4*)(A + (size_t)grow * 256 + k0 + abCol[l]);
                ap[l] = make_uint4(f2tf(v.x), f2tf(v.y), f2tf(v.z), f2tf(v.w));
                float4 w = *(const float4*)(g_WvT + (size_t)(col0 + bRow[l]) * 256 + k0 + abCol[l]);
                bp[l] = make_uint4(f2tf(w.x), f2tf(w.y), f2tf(w.z), f2tf(w.w));
            }
        }
#pragma unroll
        for (int ks = 0; ks < 4; ks++) {
            uint32_t a[4][4], b[4][2];
#pragma unroll
            for (int mt = 0; mt < 4; mt++)
#pragma unroll
                for (int rg = 0; rg < 4; rg++)
                    a[mt][rg] = As[((ks * 8 + warp_m * 4 + mt) * 4 + rg) * 32 + lane];
#pragma unroll
            for (int nt = 0; nt < 4; nt++)
#pragma unroll
                for (int rg = 0; rg < 2; rg++)
                    b[nt][rg] = Bs[((ks * 16 + warp_n * 4 + nt) * 2 + rg) * 32 + lane];
#pragma unroll
            for (int mt = 0; mt < 4; mt++)
#pragma unroll
                for (int nt = 0; nt < 4; nt++) {
                    asm volatile(
                        "mma.sync.aligned.m16n8k8.row.col.f32.tf32.tf32.f32 "
                        "{%0,%1,%2,%3}, {%4,%5,%6,%7}, {%8,%9}, {%0,%1,%2,%3};"
                        : "+f"(acc[mt][nt][0]), "+f"(acc[mt][nt][1]),
                          "+f"(acc[mt][nt][2]), "+f"(acc[mt][nt][3])
                        : "r"(a[mt][0]), "r"(a[mt][1]), "r"(a[mt][2]), "r"(a[mt][3]),
                          "r"(b[nt][0]), "r"(b[nt][1]));
                }
        }
        __syncthreads();
    }

    int g = lane >> 2, tig = lane & 3;
#pragma unroll
    for (int mt = 0; mt < 4; mt++) {
        int rbase = row0 + warp_m * 64 + mt * 16;
#pragma unroll
        for (int h = 0; h < 2; h++) {
            int grow = rbase + h * 8 + g;
            if (grow < NN) {
                __half* orow = g_xvh + (size_t)grow * 256;
#pragma unroll
                for (int nt = 0; nt < 4; nt++) {
                    int col = col0 + warp_n * 32 + nt * 8 + tig * 2;
                    float2 o;
                    o.x = acc[mt][nt][h * 2 + 0] + bias[col];
                    o.y = acc[mt][nt][h * 2 + 1] + bias[col + 1];
                    *(__half2*)(orow + col) = __floats2half2_rn(o.x, o.y);
                }
            }
        }
    }
}

// ---------------- attention + output (warp per dst node) --------------------
__global__ void k_out(float* __restrict__ out) {
    int gw = (blockIdx.x * blockDim.x + threadIdx.x) >> 5;
    int lane = threadIdx.x & 31;
    if (gw >= NN) return;
    int s0 = g_off[gw], s1 = g_off[gw + 1];
    float4* orow = (float4*)(out + (size_t)gw * 256);
    if (s0 == s1) {
        float4 z = make_float4(0.f, 0.f, 0.f, 0.f);
        orow[lane] = z; orow[lane + 32] = z;
        return;
    }
    float srh[4];
#pragma unroll
    for (int h = 0; h < 4; h++) srh[h] = g_agg[gw * 8 + 4 + h];

    float m[4] = {-3.402823466e38f, -3.402823466e38f, -3.402823466e38f, -3.402823466e38f};
    for (int j = s0 + lane; j < s1; j += 32) {
        int s = g_esrc[j];
#pragma unroll
        for (int h = 0; h < 4; h++) {
            float e = g_agg[s * 8 + h] + srh[h];
            e = e > 0.f ? e : 0.2f * e;
            m[h] = fmaxf(m[h], e);
        }
    }
#pragma unroll
    for (int h = 0; h < 4; h++)
#pragma unroll
        for (int o = 16; o; o >>= 1) m[h] = fmaxf(m[h], __shfl_xor_sync(0xffffffffu, m[h], o));

    float den0 = 0.f, den1 = 0.f, den2 = 0.f, den3 = 0.f;
    float4 acc0 = make_float4(0.f, 0.f, 0.f, 0.f);
    float4 acc1 = acc0;
    bool hi = (lane & 16) != 0;
    for (int j = s0; j < s1; j++) {
        int s = g_esrc[j];
        float e0 = g_agg[s * 8 + 0] + srh[0]; e0 = e0 > 0.f ? e0 : 0.2f * e0;
        float e1 = g_agg[s * 8 + 1] + srh[1]; e1 = e1 > 0.f ? e1 : 0.2f * e1;
        float e2 = g_agg[s * 8 + 2] + srh[2]; e2 = e2 > 0.f ? e2 : 0.2f * e2;
        float e3 = g_agg[s * 8 + 3] + srh[3]; e3 = e3 > 0.f ? e3 : 0.2f * e3;
        float x0 = __expf(e0 - m[0]);
        float x1 = __expf(e1 - m[1]);
        float x2 = __expf(e2 - m[2]);
        float x3 = __expf(e3 - m[3]);
        den0 += x0; den1 += x1; den2 += x2; den3 += x3;
        const uint2* vr = (const uint2*)(g_xvh + (size_t)s * 256);
        uint2 p0 = vr[lane], p1 = vr[lane + 32];
        float2 a0 = __half22float2(*(__half2*)&p0.x);
        float2 a1 = __half22float2(*(__half2*)&p0.y);
        float2 b0 = __half22float2(*(__half2*)&p1.x);
        float2 b1 = __half22float2(*(__half2*)&p1.y);
        float w0 = hi ? x1 : x0;
        float w1 = hi ? x3 : x2;
        acc0.x += w0 * a0.x; acc0.y += w0 * a0.y; acc0.z += w0 * a1.x; acc0.w += w0 * a1.y;
        acc1.x += w1 * b0.x; acc1.y += w1 * b0.y; acc1.z += w1 * b1.x; acc1.w += w1 * b1.y;
    }
    float d0 = hi ? den1 : den0;
    float d1 = hi ? den3 : den2;
    float i0 = 1.f / fmaxf(d0, 1e-16f);
    float i1 = 1.f / fmaxf(d1, 1e-16f);
    acc0.x *= i0; acc0.y *= i0; acc0.z *= i0; acc0.w *= i0;
    acc1.x *= i1; acc1.y *= i1; acc1.z *= i1; acc1.w *= i1;
    orow[lane] = acc0;
    orow[lane + 32] = acc1;
}

// ---------------- launch ----------------
extern "C" void kernel_launch(void* const* d_in, const int* in_sizes, int n_in,
                              void* d_out, int out_size) {
    const float* x    = (const float*)d_in[0];
    const int*   src  = (const int*)d_in[1];
    const int*   dst  = (const int*)d_in[2];
    const float* Wl   = (const float*)d_in[3];
    const float* bl   = (const float*)d_in[4];
    const float* Wr   = (const float*)d_in[5];
    const float* br   = (const float*)d_in[6];
    const float* Wv   = (const float*)d_in[7];
    const float* bv   = (const float*)d_in[8];
    const float* attl = (const float*)d_in[9];
    const float* attr = (const float*)d_in[10];
    float* out = (float*)d_out;

    k_setup<<<72 + (NN + 255) / 256, 256>>>(Wl, bl, Wr, br, attl, attr, Wv);
    k_hlr<<<(NN + 255) / 256, 256>>>(x);
    k_count<<<(EE + 255) / 256, 256>>>(dst);
    k_bsum<<<NB, 1024>>>();
    k_bscan<<<1, 64>>>();
    k_scan2<<<NB, 1024>>>();
    k_scatter<<<(EE + 255) / 256, 256>>>(src, dst);
    k_gemm_mma<<<((NN + 127) / 128) * 2, 256>>>(x, bv);
    k_agg<<<(NN * 8 + 255) / 256, 256>>>();
    k_out<<<(NN * 32 + 255) / 256, 256>>>(out);
}